// round 10
// baseline (speedup 1.0000x reference)
#include <cuda_runtime.h>
typedef unsigned long long u64;

#define T_STEPS 32
#define BB      32
#define NIN     512
#define NH      1024
#define NOUT    256
#define NBLK    148
#define NTHR    512
#define KC      64
#define KCL     128

// ---- device scratch (all activation tensors transposed [j][b]) ----
__device__ float g_sT  [T_STEPS][NH * BB];
__device__ float g_zT  [T_STEPS][NH * BB];
__device__ float g_zcT [T_STEPS][NH * BB];
__device__ float g_histT[T_STEPS][NH * BB];
__device__ float g_h   [NH * BB];
__device__ float g_P   [16][NH * BB];
__device__ float g_Q   [8][NH * BB];
__device__ float g_d   [T_STEPS][BB];
__device__ float g_yP  [8][NOUT * BB];
__device__ unsigned g_cnt;

// ---- f32x2 helpers ----
__device__ __forceinline__ u64 pk2(float lo, float hi) {
    u64 r; asm("mov.b64 %0, {%1, %2};" : "=l"(r) : "f"(lo), "f"(hi)); return r;
}
__device__ __forceinline__ void upk2(u64 v, float& lo, float& hi) {
    asm("mov.b64 {%0, %1}, %2;" : "=f"(lo), "=f"(hi) : "l"(v));
}
__device__ __forceinline__ u64 fma2(u64 a, u64 b, u64 c) {
    u64 d; asm("fma.rn.f32x2 %0, %1, %2, %3;" : "=l"(d) : "l"(a), "l"(b), "l"(c));
    return d;
}

// ---- grid barrier (wrap-safe monotonic) ----
__device__ __forceinline__ void gsync() {
    __syncthreads();
    if (threadIdx.x == 0) {
        __threadfence();
        unsigned a = atomicAdd(&g_cnt, 1u);
        unsigned target = (a / NBLK + 1u) * NBLK;
        while ((int)(*(volatile unsigned*)&g_cnt - target) < 0) { }
        __threadfence();
    }
    __syncthreads();
}

// ---- shared memory ----
union ShU {
    struct { float As[KC][36];  float Ws[KC][128]; } pro;   // 41 KB
    struct { float Wh[KCL][128]; float As[KCL][36]; } loop; // 82 KB
    struct { float dsum[16][32]; } dot;
};

// ---- inner product core: KK kk-steps, 8 rows x 1 col per thread ----
template<int KK>
__device__ __forceinline__ void compute_k(const float (*As)[36], const float (*Ws)[128],
                                          int rg, int tw, u64& a0, u64& a1, u64& a2, u64& a3)
{
#pragma unroll 16
    for (int kk = 0; kk < KK; ++kk) {
        float w = Ws[kk][tw];
        u64 w2 = pk2(w, w);
        ulonglong2 p01 = *(const ulonglong2*)&As[kk][rg * 8];
        ulonglong2 p23 = *(const ulonglong2*)&As[kk][rg * 8 + 4];
        a0 = fma2(p01.x, w2, a0);
        a1 = fma2(p01.y, w2, a1);
        a2 = fma2(p23.x, w2, a2);
        a3 = fma2(p23.y, w2, a3);
    }
}

__device__ __forceinline__ void write_outT(float* outT, int j, int rg,
                                           u64 a0, u64 a1, u64 a2, u64 a3, bool relu)
{
    float o[8];
    upk2(a0, o[0], o[1]); upk2(a1, o[2], o[3]);
    upk2(a2, o[4], o[5]); upk2(a3, o[6], o[7]);
    if (relu) {
#pragma unroll
        for (int r = 0; r < 8; ++r) o[r] = fmaxf(o[r], 0.0f);
    }
    float* op = outT + (size_t)j * BB + rg * 8;
    *(float4*)op       = make_float4(o[0], o[1], o[2], o[3]);
    *(float4*)(op + 4) = make_float4(o[4], o[5], o[6], o[7]);
}

// ---- GEMM, row-major A (x_in only), transposed out, reg double-buffered -
template<bool RELU_IN, int KA>
__device__ __forceinline__ void gemm_proR(ShU* sh,
    const float* __restrict__ A0, int rbase,
    const float* __restrict__ W, int klen,
    float* __restrict__ outT, int colbase)
{
    const int tid = threadIdx.x, lane = tid & 31, wg = tid >> 5;
    const int colq = wg >> 2, rg = wg & 3;
    const int tw = colq * 32 + lane, j = colbase + tw;
    u64 a0 = 0, a1 = 0, a2 = 0, a3 = 0;
    float av[4]; float4 wr[4];

#pragma unroll
    for (int u = 0; u < 4; ++u) {
        int kk = lane + ((u & 1) << 5), b = wg * 2 + (u >> 1);
        float v = A0[(size_t)(rbase + b) * KA + kk];
        av[u] = RELU_IN ? fmaxf(v, 0.0f) : v;
    }
#pragma unroll
    for (int u = 0; u < 4; ++u)
        wr[u] = *(const float4*)&W[(size_t)(wg * 4 + u) * NH + colbase + lane * 4];

    for (int kb = 0; kb < klen; kb += KC) {
        __syncthreads();
#pragma unroll
        for (int u = 0; u < 4; ++u) {
            int kk = lane + ((u & 1) << 5), b = wg * 2 + (u >> 1);
            sh->pro.As[kk][b] = av[u];
        }
#pragma unroll
        for (int u = 0; u < 4; ++u)
            *(float4*)&sh->pro.Ws[wg * 4 + u][lane * 4] = wr[u];
        __syncthreads();
        if (kb + KC < klen) {
            int kn = kb + KC;
#pragma unroll
            for (int u = 0; u < 4; ++u) {
                int kk = lane + ((u & 1) << 5), b = wg * 2 + (u >> 1);
                float v = A0[(size_t)(rbase + b) * KA + kn + kk];
                av[u] = RELU_IN ? fmaxf(v, 0.0f) : v;
            }
#pragma unroll
            for (int u = 0; u < 4; ++u)
                wr[u] = *(const float4*)&W[(size_t)(kn + wg * 4 + u) * NH + colbase + lane * 4];
        }
        compute_k<KC>(sh->pro.As, sh->pro.Ws, rg, tw, a0, a1, a2, a3);
    }
    write_outT(outT, j, rg, a0, a1, a2, a3, true);
}

// ---- GEMM, transposed [k][b] A (+NPART stream combine), transposed out --
template<int NPART, bool RELU_IN, bool RELU_OUT, int N>
__device__ __forceinline__ void gemm_proT(ShU* sh,
    const float* __restrict__ A0T, size_t pstr,
    const float* __restrict__ W, int k0, int klen,
    float* __restrict__ outT, int colbase)
{
    const int tid = threadIdx.x, lane = tid & 31, wg = tid >> 5;
    const int colq = wg >> 2, rg = wg & 3;
    const int tw = colq * 32 + lane, j = colbase + tw;
    const int kk = tid >> 3, bq = tid & 7;
    u64 a0 = 0, a1 = 0, a2 = 0, a3 = 0;
    float4 av; float4 wr[4];

    {
        const float* ap = A0T + (size_t)(k0 + kk) * BB + bq * 4;
        av = *(const float4*)ap;
#pragma unroll
        for (int p = 1; p < NPART; ++p) {
            float4 x = *(const float4*)(ap + (size_t)p * pstr);
            av.x += x.x; av.y += x.y; av.z += x.z; av.w += x.w;
        }
        if (RELU_IN) {
            av.x = fmaxf(av.x, 0.0f); av.y = fmaxf(av.y, 0.0f);
            av.z = fmaxf(av.z, 0.0f); av.w = fmaxf(av.w, 0.0f);
        }
    }
#pragma unroll
    for (int u = 0; u < 4; ++u)
        wr[u] = *(const float4*)&W[(size_t)(k0 + wg * 4 + u) * N + colbase + lane * 4];

    for (int kb = 0; kb < klen; kb += KC) {
        __syncthreads();
        *(float4*)&sh->pro.As[kk][bq * 4] = av;
#pragma unroll
        for (int u = 0; u < 4; ++u)
            *(float4*)&sh->pro.Ws[wg * 4 + u][lane * 4] = wr[u];
        __syncthreads();
        if (kb + KC < klen) {
            int kn = k0 + kb + KC;
            const float* ap = A0T + (size_t)(kn + kk) * BB + bq * 4;
            av = *(const float4*)ap;
#pragma unroll
            for (int p = 1; p < NPART; ++p) {
                float4 x = *(const float4*)(ap + (size_t)p * pstr);
                av.x += x.x; av.y += x.y; av.z += x.z; av.w += x.w;
            }
            if (RELU_IN) {
                av.x = fmaxf(av.x, 0.0f); av.y = fmaxf(av.y, 0.0f);
                av.z = fmaxf(av.z, 0.0f); av.w = fmaxf(av.w, 0.0f);
            }
#pragma unroll
            for (int u = 0; u < 4; ++u)
                wr[u] = *(const float4*)&W[(size_t)(kn + wg * 4 + u) * N + colbase + lane * 4];
        }
        compute_k<KC>(sh->pro.As, sh->pro.Ws, rg, tw, a0, a1, a2, a3);
    }
    write_outT(outT, j, rg, a0, a1, a2, a3, RELU_OUT);
}

// ---- loop GEMM: persistent Wh[128][128], 1 chunk, transposed A/out ------
__device__ __forceinline__ void gemm_loopT(ShU* sh,
    const float* __restrict__ A0T, int k0,
    float* __restrict__ outT, int colbase)
{
    const int tid = threadIdx.x, lane = tid & 31, wg = tid >> 5;
    const int colq = wg >> 2, rg = wg & 3;
    const int tw = colq * 32 + lane, j = colbase + tw;
    u64 a0 = 0, a1 = 0, a2 = 0, a3 = 0;

    __syncthreads();
#pragma unroll
    for (int u = 0; u < 2; ++u) {
        int idx = u * 512 + tid;
        int kk = idx >> 3, bq = idx & 7;
        *(float4*)&sh->loop.As[kk][bq * 4] =
            *(const float4*)(A0T + (size_t)(k0 + kk) * BB + bq * 4);
    }
    __syncthreads();
    compute_k<KCL>(sh->loop.As, sh->loop.Wh, rg, tw, a0, a1, a2, a3);
    write_outT(outT, j, rg, a0, a1, a2, a3, false);
}

// ---- persistent kernel ----
__global__ void __launch_bounds__(NTHR, 1) memnet_kernel(
    const float* __restrict__ x_in,  const float* __restrict__ W_i,
    const float* __restrict__ W_z,   const float* __restrict__ W_c,
    const float* __restrict__ W_h,   const float* __restrict__ W_ho,
    const float* __restrict__ W_o,   const float* __restrict__ lam_p,
    const float* __restrict__ eta_p, const float* __restrict__ g_p,
    const float* __restrict__ b_p,   float* __restrict__ y_out)
{
    extern __shared__ char dsm[];
    ShU* sh = (ShU*)dsm;

    const int tid  = threadIdx.x;
    const int bid  = blockIdx.x;
    const int lane = tid & 31;
    const int wg   = tid >> 5;
    const int gtid = bid * NTHR + tid;

    const float lamv = lam_p[0];
    const float etav = eta_p[0];

    // ===== Prologue: x -> s -> z -> zc, all transposed [t][j][b] =====
    for (int task = bid; task < 256; task += NBLK) {
        int rb = task >> 3, cb = task & 7;
        gemm_proR<true, NIN>(sh, x_in, rb * 32, W_i, NIN,
                             g_sT[rb], cb * 128);
    }
    gsync();
    for (int task = bid; task < 256; task += NBLK) {
        int rb = task >> 3, cb = task & 7;
        gemm_proT<1, false, true, NH>(sh, g_sT[rb], 0, W_z, 0, NH,
                                      g_zT[rb], cb * 128);
    }
    gsync();
    for (int task = bid; task < 256; task += NBLK) {
        int rb = task >> 3, cb = task & 7;
        gemm_proT<1, false, false, NH>(sh, g_zT[rb], 0, W_c, 0, NH,
                                       g_zcT[rb], cb * 128);
    }
    gsync();
    // load persistent 128x128 W_h tile (GEMM CTAs only)
    if (bid < 64) {
        int ks = bid >> 3, cb = bid & 7;
#pragma unroll
        for (int u = 0; u < 8; ++u) {
            int kk = wg * 8 + u;
            *(float4*)&sh->loop.Wh[kk][lane * 4] =
                *(const float4*)&W_h[(size_t)(ks * 128 + kk) * NH + cb * 128 + lane * 4];
        }
    }
    gsync();

    // ===== Recurrent loop =====
    for (int t = 0; t < T_STEPS; ++t) {
        // ---- A: P[ks] = h @ W_h tile (skip t=0) ----
        if (t > 0) {
            if (bid < 64) {
                int ks = bid >> 3, cb = bid & 7;
                gemm_loopT(sh, g_h, ks * 128, g_P[ks], cb * 128);
            }
            gsync();
        }

        // ---- B: hist[t] = relu(zc + sum P) (all CTAs, coalesced) ----
        if (gtid < NH * BB / 4) {
            size_t off = (size_t)gtid * 4;
            float4 v = *(const float4*)&g_zcT[t][off];
            if (t > 0) {
#pragma unroll
                for (int p = 0; p < 8; ++p) {
                    float4 x = *(const float4*)&g_P[p][off];
                    v.x += x.x; v.y += x.y; v.z += x.z; v.w += x.w;
                }
            }
            v.x = fmaxf(v.x, 0.0f); v.y = fmaxf(v.y, 0.0f);
            v.z = fmaxf(v.z, 0.0f); v.w = fmaxf(v.w, 0.0f);
            *(float4*)&g_histT[t][off] = v;
        }
        gsync();

        // ---- C: Q[ks] = hist[t] @ W_h tile  ||  dots d[s][b] ----
        if (bid < 64) {
            int ks = bid >> 3, cb = bid & 7;
            gemm_loopT(sh, g_histT[t], ks * 128, g_Q[ks], cb * 128);
        } else {
            int s = bid - 64;
            if (s <= t) {
                const float* ht = g_histT[t];
                const float* hs = g_histT[s];
                float sum = 0.0f;
#pragma unroll 8
                for (int jj = wg * 64; jj < wg * 64 + 64; ++jj)
                    sum = fmaf(ht[(size_t)jj * BB + lane],
                               hs[(size_t)jj * BB + lane], sum);
                sh->dot.dsum[wg][lane] = sum;
                __syncthreads();
                if (wg == 0) {
                    float tot = 0.0f;
#pragma unroll
                    for (int w = 0; w < 16; ++w) tot += sh->dot.dsum[w][lane];
                    g_d[s][lane] = tot;
                }
            }
        }
        gsync();

        // ---- D: fused readout + batchnorm, warp-per-j (64 CTAs) ----
        if (bid < 64) {
            int j = bid * 16 + wg;
            size_t off = (size_t)j * BB + lane;
            float v = g_zcT[t][off];
#pragma unroll
            for (int p = 0; p < 8; ++p) v += g_Q[p][off];
            float accr = 0.0f, pw = etav;
            for (int s = t; s >= 0; --s) {
                accr = fmaf(pw * g_d[s][lane], g_histT[s][off], accr);
                pw *= lamv;
            }
            v += accr;
            // batch mean over lanes
            float mu = v;
#pragma unroll
            for (int o = 16; o; o >>= 1) mu += __shfl_xor_sync(~0u, mu, o);
            mu *= (1.0f / BB);
            float dv = v - mu;
            float sq = dv * dv;
#pragma unroll
            for (int o = 16; o; o >>= 1) sq += __shfl_xor_sync(~0u, sq, o);
            float sig = sqrtf(sq * (1.0f / BB));
            g_h[off] = fmaxf(g_p[j] * dv / sig + b_p[j], 0.0f);
        }
        gsync();
    }

    // ===== Epilogue =====
    // E1: P[ks] = h @ W_ho slices (128 tasks)
    if (bid < 128) {
        int ks = bid >> 3, cb = bid & 7;
        gemm_proT<1, false, false, NH>(sh, g_h, 0, W_ho, ks * 64, 64,
                                       g_P[ks], cb * 128);
    }
    gsync();
    // E2: yP[ks] = relu(sum16 P) @ W_o slices (16 tasks)
    if (bid < 16) {
        int ks = bid >> 1, cb = bid & 1;
        gemm_proT<16, true, false, NOUT>(sh, g_P[0], (size_t)NH * BB,
                                         W_o, ks * 128, 128,
                                         g_yP[ks], cb * 128);
    }
    gsync();
    // E3: y[b][j] = relu(sum8 yP[j][b])
    if (gtid < NOUT * BB) {
        int j = gtid >> 5, b = gtid & 31;
        float v = 0.0f;
#pragma unroll
        for (int p = 0; p < 8; ++p) v += g_yP[p][(size_t)j * BB + b];
        y_out[(size_t)b * NOUT + j] = fmaxf(v, 0.0f);
    }
}

// ---- launch ----
extern "C" void kernel_launch(void* const* d_in, const int* in_sizes, int n_in,
                              void* d_out, int out_size) {
    (void)in_sizes; (void)n_in; (void)out_size;
    static int s_attr_done = 0;
    if (!s_attr_done) {
        cudaFuncSetAttribute(memnet_kernel,
                             cudaFuncAttributeMaxDynamicSharedMemorySize,
                             (int)sizeof(ShU));
        s_attr_done = 1;
    }
    memnet_kernel<<<NBLK, NTHR, sizeof(ShU)>>>(
        (const float*)d_in[0],  (const float*)d_in[1], (const float*)d_in[2],
        (const float*)d_in[3],  (const float*)d_in[4], (const float*)d_in[5],
        (const float*)d_in[6],  (const float*)d_in[7], (const float*)d_in[8],
        (const float*)d_in[9],  (const float*)d_in[10], (float*)d_out);
}

// round 15
// speedup vs baseline: 1.2183x; 1.2183x over previous
#include <cuda_runtime.h>
typedef unsigned long long u64;

#define T_STEPS 32
#define BB      32
#define NIN     512
#define NH      1024
#define NOUT    256
#define NBLK    148
#define NTHR    512
#define KC      64
#define NHELP   20

// ---- device scratch (activations transposed [j][b]) ----
__device__ float g_sT  [T_STEPS][NH * BB];
__device__ float g_zT  [T_STEPS][NH * BB];
__device__ float g_zcT [T_STEPS][NH * BB];
__device__ float g_histT[T_STEPS][NH * BB];
__device__ float g_h   [NH * BB];
__device__ float g_P   [16][NH * BB];
__device__ float g_Q   [16][NH * BB];
__device__ float g_d   [T_STEPS][BB];
__device__ float g_yP  [8][NOUT * BB];
__device__ unsigned g_cnt, g_cnt2;

// ---- f32x2 helpers ----
__device__ __forceinline__ u64 pk2(float lo, float hi) {
    u64 r; asm("mov.b64 %0, {%1, %2};" : "=l"(r) : "f"(lo), "f"(hi)); return r;
}
__device__ __forceinline__ void upk2(u64 v, float& lo, float& hi) {
    asm("mov.b64 {%0, %1}, %2;" : "=f"(lo), "=f"(hi) : "l"(v));
}
__device__ __forceinline__ u64 fma2(u64 a, u64 b, u64 c) {
    u64 d; asm("fma.rn.f32x2 %0, %1, %2, %3;" : "=l"(d) : "l"(a), "l"(b), "l"(c));
    return d;
}

// ---- grid barriers (wrap-safe monotonic) ----
__device__ __forceinline__ void gsync() {
    __syncthreads();
    if (threadIdx.x == 0) {
        __threadfence();
        unsigned a = atomicAdd(&g_cnt, 1u);
        unsigned target = (a / NBLK + 1u) * NBLK;
        while ((int)(*(volatile unsigned*)&g_cnt - target) < 0) { }
        __threadfence();
    }
    __syncthreads();
}
__device__ __forceinline__ void gsync2() {   // helper CTAs only (NHELP)
    __syncthreads();
    if (threadIdx.x == 0) {
        __threadfence();
        unsigned a = atomicAdd(&g_cnt2, 1u);
        unsigned target = (a / NHELP + 1u) * NHELP;
        while ((int)(*(volatile unsigned*)&g_cnt2 - target) < 0) { }
        __threadfence();
    }
    __syncthreads();
}

// ---- shared memory (42 KB, under 48 KB default) ----
union ShU {
    struct { float As[KC][36]; float Ws[KC][128]; } pro;
    struct { float Wh[KC][128]; float As[KC][36]; } loop;
    struct { float dsum[16][32]; } dot;
};

// ---- inner core: KK kk-steps, 8 rows x 1 col per thread ----
template<int KK>
__device__ __forceinline__ void compute_k(const float (*As)[36], const float (*Ws)[128],
                                          int rg, int tw, u64& a0, u64& a1, u64& a2, u64& a3)
{
#pragma unroll 16
    for (int kk = 0; kk < KK; ++kk) {
        float w = Ws[kk][tw];
        u64 w2 = pk2(w, w);
        ulonglong2 p01 = *(const ulonglong2*)&As[kk][rg * 8];
        ulonglong2 p23 = *(const ulonglong2*)&As[kk][rg * 8 + 4];
        a0 = fma2(p01.x, w2, a0);
        a1 = fma2(p01.y, w2, a1);
        a2 = fma2(p23.x, w2, a2);
        a3 = fma2(p23.y, w2, a3);
    }
}

__device__ __forceinline__ void write_outT(float* outT, int j, int rg,
                                           u64 a0, u64 a1, u64 a2, u64 a3, bool relu)
{
    float o[8];
    upk2(a0, o[0], o[1]); upk2(a1, o[2], o[3]);
    upk2(a2, o[4], o[5]); upk2(a3, o[6], o[7]);
    if (relu) {
#pragma unroll
        for (int r = 0; r < 8; ++r) o[r] = fmaxf(o[r], 0.0f);
    }
    float* op = outT + (size_t)j * BB + rg * 8;
    *(float4*)op       = make_float4(o[0], o[1], o[2], o[3]);
    *(float4*)(op + 4) = make_float4(o[4], o[5], o[6], o[7]);
}

// ---- GEMM, row-major A (x_in only), transposed out ----
template<bool RELU_IN, int KA>
__device__ __forceinline__ void gemm_proR(ShU* sh,
    const float* __restrict__ A0, int rbase,
    const float* __restrict__ W, int klen,
    float* __restrict__ outT, int colbase)
{
    const int tid = threadIdx.x, lane = tid & 31, wg = tid >> 5;
    const int colq = wg >> 2, rg = wg & 3;
    const int tw = colq * 32 + lane, j = colbase + tw;
    u64 a0 = 0, a1 = 0, a2 = 0, a3 = 0;
    float av[4]; float4 wr[4];

#pragma unroll
    for (int u = 0; u < 4; ++u) {
        int kk = lane + ((u & 1) << 5), b = wg * 2 + (u >> 1);
        float v = A0[(size_t)(rbase + b) * KA + kk];
        av[u] = RELU_IN ? fmaxf(v, 0.0f) : v;
    }
#pragma unroll
    for (int u = 0; u < 4; ++u)
        wr[u] = *(const float4*)&W[(size_t)(wg * 4 + u) * NH + colbase + lane * 4];

    for (int kb = 0; kb < klen; kb += KC) {
        __syncthreads();
#pragma unroll
        for (int u = 0; u < 4; ++u) {
            int kk = lane + ((u & 1) << 5), b = wg * 2 + (u >> 1);
            sh->pro.As[kk][b] = av[u];
        }
#pragma unroll
        for (int u = 0; u < 4; ++u)
            *(float4*)&sh->pro.Ws[wg * 4 + u][lane * 4] = wr[u];
        __syncthreads();
        if (kb + KC < klen) {
            int kn = kb + KC;
#pragma unroll
            for (int u = 0; u < 4; ++u) {
                int kk = lane + ((u & 1) << 5), b = wg * 2 + (u >> 1);
                float v = A0[(size_t)(rbase + b) * KA + kn + kk];
                av[u] = RELU_IN ? fmaxf(v, 0.0f) : v;
            }
#pragma unroll
            for (int u = 0; u < 4; ++u)
                wr[u] = *(const float4*)&W[(size_t)(kn + wg * 4 + u) * NH + colbase + lane * 4];
        }
        compute_k<KC>(sh->pro.As, sh->pro.Ws, rg, tw, a0, a1, a2, a3);
    }
    write_outT(outT, j, rg, a0, a1, a2, a3, true);
}

// ---- GEMM, transposed [k][b] A (+NPART-1 partial streams), transp out ----
template<int NPART, bool RELU_IN, bool RELU_OUT, int N>
__device__ __forceinline__ void gemm_proT(ShU* sh,
    const float* __restrict__ A0T, size_t pstr,
    const float* __restrict__ W, int k0, int klen,
    float* __restrict__ outT, int colbase)
{
    const int tid = threadIdx.x, lane = tid & 31, wg = tid >> 5;
    const int colq = wg >> 2, rg = wg & 3;
    const int tw = colq * 32 + lane, j = colbase + tw;
    const int kk = tid >> 3, bq = tid & 7;
    u64 a0 = 0, a1 = 0, a2 = 0, a3 = 0;
    float4 av; float4 wr[4];

    {
        const float* ap = A0T + (size_t)(k0 + kk) * BB + bq * 4;
        av = *(const float4*)ap;
#pragma unroll
        for (int p = 1; p < NPART; ++p) {
            float4 x = *(const float4*)(ap + (size_t)p * pstr);
            av.x += x.x; av.y += x.y; av.z += x.z; av.w += x.w;
        }
        if (RELU_IN) {
            av.x = fmaxf(av.x, 0.0f); av.y = fmaxf(av.y, 0.0f);
            av.z = fmaxf(av.z, 0.0f); av.w = fmaxf(av.w, 0.0f);
        }
    }
#pragma unroll
    for (int u = 0; u < 4; ++u)
        wr[u] = *(const float4*)&W[(size_t)(k0 + wg * 4 + u) * N + colbase + lane * 4];

    for (int kb = 0; kb < klen; kb += KC) {
        __syncthreads();
        *(float4*)&sh->pro.As[kk][bq * 4] = av;
#pragma unroll
        for (int u = 0; u < 4; ++u)
            *(float4*)&sh->pro.Ws[wg * 4 + u][lane * 4] = wr[u];
        __syncthreads();
        if (kb + KC < klen) {
            int kn = k0 + kb + KC;
            const float* ap = A0T + (size_t)(kn + kk) * BB + bq * 4;
            av = *(const float4*)ap;
#pragma unroll
            for (int p = 1; p < NPART; ++p) {
                float4 x = *(const float4*)(ap + (size_t)p * pstr);
                av.x += x.x; av.y += x.y; av.z += x.z; av.w += x.w;
            }
            if (RELU_IN) {
                av.x = fmaxf(av.x, 0.0f); av.y = fmaxf(av.y, 0.0f);
                av.z = fmaxf(av.z, 0.0f); av.w = fmaxf(av.w, 0.0f);
            }
#pragma unroll
            for (int u = 0; u < 4; ++u)
                wr[u] = *(const float4*)&W[(size_t)(kn + wg * 4 + u) * N + colbase + lane * 4];
        }
        compute_k<KC>(sh->pro.As, sh->pro.Ws, rg, tw, a0, a1, a2, a3);
    }
    write_outT(outT, j, rg, a0, a1, a2, a3, RELU_OUT);
}

// ---- loop GEMM: persistent Wh[64][128]; staging combines NEXTRA partials -
template<int NEXTRA, bool RELU>
__device__ __forceinline__ void gemm_loopT(ShU* sh,
    const float* __restrict__ A0T, int k0,
    const float* __restrict__ Pb,
    float* __restrict__ outT, int colbase)
{
    const int tid = threadIdx.x, lane = tid & 31, wg = tid >> 5;
    const int colq = wg >> 2, rg = wg & 3;
    const int tw = colq * 32 + lane, j = colbase + tw;
    const int kk = tid >> 3, bq = tid & 7;
    u64 a0 = 0, a1 = 0, a2 = 0, a3 = 0;

    __syncthreads();
    {
        size_t eo = (size_t)(k0 + kk) * BB + bq * 4;
        float4 av = *(const float4*)(A0T + eo);
#pragma unroll
        for (int p = 0; p < NEXTRA; ++p) {
            float4 x = *(const float4*)(Pb + (size_t)p * (NH * BB) + eo);
            av.x += x.x; av.y += x.y; av.z += x.z; av.w += x.w;
        }
        if (RELU) {
            av.x = fmaxf(av.x, 0.0f); av.y = fmaxf(av.y, 0.0f);
            av.z = fmaxf(av.z, 0.0f); av.w = fmaxf(av.w, 0.0f);
        }
        *(float4*)&sh->loop.As[kk][bq * 4] = av;
    }
    __syncthreads();
    compute_k<KC>(sh->loop.As, sh->loop.Wh, rg, tw, a0, a1, a2, a3);
    write_outT(outT, j, rg, a0, a1, a2, a3, false);
}

// ---- persistent kernel ----
__global__ void __launch_bounds__(NTHR, 1) memnet_kernel(
    const float* __restrict__ x_in,  const float* __restrict__ W_i,
    const float* __restrict__ W_z,   const float* __restrict__ W_c,
    const float* __restrict__ W_h,   const float* __restrict__ W_ho,
    const float* __restrict__ W_o,   const float* __restrict__ lam_p,
    const float* __restrict__ eta_p, const float* __restrict__ g_p,
    const float* __restrict__ b_p,   float* __restrict__ y_out)
{
    extern __shared__ char dsm[];
    ShU* sh = (ShU*)dsm;

    const int tid  = threadIdx.x;
    const int bid  = blockIdx.x;
    const int lane = tid & 31;
    const int wg   = tid >> 5;
    const int gtid = bid * NTHR + tid;

    const float lamv = lam_p[0];
    const float etav = eta_p[0];

    // ===== Prologue: x -> s -> z -> zc (transposed outputs) =====
    for (int task = bid; task < 256; task += NBLK) {
        int rb = task >> 3, cb = task & 7;
        gemm_proR<true, NIN>(sh, x_in, rb * 32, W_i, NIN, g_sT[rb], cb * 128);
    }
    gsync();
    for (int task = bid; task < 256; task += NBLK) {
        int rb = task >> 3, cb = task & 7;
        gemm_proT<1, false, true, NH>(sh, g_sT[rb], 0, W_z, 0, NH,
                                      g_zT[rb], cb * 128);
    }
    gsync();
    for (int task = bid; task < 256; task += NBLK) {
        int rb = task >> 3, cb = task & 7;
        gemm_proT<1, false, false, NH>(sh, g_zT[rb], 0, W_c, 0, NH,
                                       g_zcT[rb], cb * 128);
    }
    gsync();
    // persistent W_h tile: CTA (ks,cb) owns rows ks*64..+64, cols cb*128..+128
    const int ksG = bid >> 3, cbG = bid & 7;   // valid for bid<128
    if (bid < 128) {
#pragma unroll
        for (int u = 0; u < 4; ++u) {
            int kk = wg * 4 + u;
            *(float4*)&sh->loop.Wh[kk][lane * 4] =
                *(const float4*)&W_h[(size_t)(ksG * 64 + kk) * NH + cbG * 128 + lane * 4];
        }
    }
    gsync();

    // ===== Recurrent loop: 3 phases/step =====
    for (int t = 0; t < T_STEPS; ++t) {
        // ---- A: P[ks] = h @ W_h tile (skip t=0) ----
        if (t > 0) {
            if (bid < 128)
                gemm_loopT<0, false>(sh, g_h, ksG * 64, 0, g_P[ksG], cbG * 128);
            gsync();
        }

        // ---- C: Q[ks] = relu(zc+sumP) @ W_h (staging combine)
        //         || helpers: materialize histT[t], mini-barrier, dots ----
        if (bid < 128) {
            if (t == 0)
                gemm_loopT<0, true>(sh, g_zcT[t], ksG * 64, 0, g_Q[ksG], cbG * 128);
            else
                gemm_loopT<16, true>(sh, g_zcT[t], ksG * 64, g_P[0], g_Q[ksG], cbG * 128);
        } else {
            // materialize histT[t] = relu(zc + sum16 P), slice per helper CTA
            for (int idx = (bid - 128) * NTHR + tid; idx < NH * BB / 4;
                 idx += NHELP * NTHR) {
                size_t off = (size_t)idx * 4;
                float4 v = *(const float4*)&g_zcT[t][off];
                if (t > 0) {
#pragma unroll
                    for (int p = 0; p < 16; ++p) {
                        float4 x = *(const float4*)&g_P[p][off];
                        v.x += x.x; v.y += x.y; v.z += x.z; v.w += x.w;
                    }
                }
                v.x = fmaxf(v.x, 0.0f); v.y = fmaxf(v.y, 0.0f);
                v.z = fmaxf(v.z, 0.0f); v.w = fmaxf(v.w, 0.0f);
                *(float4*)&g_histT[t][off] = v;
            }
            gsync2();
            // dots d[s][b] = h_t . h_s
            for (int s = bid - 128; s <= t; s += NHELP) {
                const float* ht = g_histT[t];
                const float* hs = g_histT[s];
                float sum = 0.0f;
#pragma unroll 8
                for (int jj = wg * 64; jj < wg * 64 + 64; ++jj)
                    sum = fmaf(ht[(size_t)jj * BB + lane],
                               hs[(size_t)jj * BB + lane], sum);
                sh->dot.dsum[wg][lane] = sum;
                __syncthreads();
                if (wg == 0) {
                    float tot = 0.0f;
#pragma unroll
                    for (int w = 0; w < 16; ++w) tot += sh->dot.dsum[w][lane];
                    g_d[s][lane] = tot;
                }
                __syncthreads();
            }
        }
        gsync();

        // ---- D: fused readout + batchnorm (warp-per-column, 64 CTAs) ----
        if (bid < 64) {
            int j = bid * 16 + wg;
            size_t off = (size_t)j * BB + lane;
            float v = g_zcT[t][off];
#pragma unroll
            for (int p = 0; p < 16; ++p) v += g_Q[p][off];
            float accr = 0.0f, pw = etav;
            for (int s = t; s >= 0; --s) {
                accr = fmaf(pw * g_d[s][lane], g_histT[s][off], accr);
                pw *= lamv;
            }
            v += accr;
            float mu = v;
#pragma unroll
            for (int o = 16; o; o >>= 1) mu += __shfl_xor_sync(~0u, mu, o);
            mu *= (1.0f / BB);
            float dv = v - mu;
            float sq = dv * dv;
#pragma unroll
            for (int o = 16; o; o >>= 1) sq += __shfl_xor_sync(~0u, sq, o);
            float sig = sqrtf(sq * (1.0f / BB));
            g_h[off] = fmaxf(g_p[j] * dv / sig + b_p[j], 0.0f);
        }
        gsync();
    }

    // ===== Epilogue =====
    // E1: P[ks] = h @ W_ho slices (128 tasks)
    if (bid < 128)
        gemm_proT<1, false, false, NH>(sh, g_h, 0, W_ho, ksG * 64, 64,
                                       g_P[ksG], cbG * 128);
    gsync();
    // E2: yP[ks] = relu(sum16 P) @ W_o slices (16 tasks)
    if (bid < 16) {
        int ks = bid >> 1, cb = bid & 1;
        gemm_proT<16, true, false, NOUT>(sh, g_P[0], (size_t)NH * BB,
                                         W_o, ks * 128, 128,
                                         g_yP[ks], cb * 128);
    }
    gsync();
    // E3: y[b][j] = relu(sum8 yP[j][b])
    if (gtid < NOUT * BB) {
        int j = gtid >> 5, b = gtid & 31;
        float v = 0.0f;
#pragma unroll
        for (int p = 0; p < 8; ++p) v += g_yP[p][(size_t)j * BB + b];
        y_out[(size_t)b * NOUT + j] = fmaxf(v, 0.0f);
    }
}

// ---- launch ----
extern "C" void kernel_launch(void* const* d_in, const int* in_sizes, int n_in,
                              void* d_out, int out_size) {
    (void)in_sizes; (void)n_in; (void)out_size;
    memnet_kernel<<<NBLK, NTHR, sizeof(ShU)>>>(
        (const float*)d_in[0],  (const float*)d_in[1], (const float*)d_in[2],
        (const float*)d_in[3],  (const float*)d_in[4], (const float*)d_in[5],
        (const float*)d_in[6],  (const float*)d_in[7], (const float*)d_in[8],
        (const float*)d_in[9],  (const float*)d_in[10], (float*)d_out);
}